// round 1
// baseline (speedup 1.0000x reference)
#include <cuda_runtime.h>
#include <cstdint>

// Problem constants (fixed shapes for this problem instance)
#define NMAX 100000
#define INDIM 256

// ---------------- device scratch (no runtime allocation allowed) ----------------
__device__ float g_h [NMAX * 64];    // message-MLP output (reused layer1/layer2)
__device__ float g_m [NMAX * 64];    // aggregation accumulator (reused)
__device__ float g_x1[NMAX * 128];   // layer-1 output
__device__ float g_x2[NMAX * 64];    // layer-2 output
__device__ float g_deg[NMAX];        // degree -> inv degree

// ---------------- small utility kernels ----------------
__global__ void zero_kernel(float* __restrict__ p, int n) {
    int i = blockIdx.x * blockDim.x + threadIdx.x;
    if (i < n) p[i] = 0.f;
}

__global__ void degree_kernel(const int* __restrict__ dst, float* __restrict__ deg, int E) {
    int e = blockIdx.x * blockDim.x + threadIdx.x;
    if (e < E) atomicAdd(&deg[dst[e]], 1.0f);
}

__global__ void invdeg_kernel(float* __restrict__ deg, int n) {
    int i = blockIdx.x * blockDim.x + threadIdx.x;
    if (i < n) deg[i] = 1.0f / fmaxf(deg[i], 1.0f);
}

// ---------------- scatter-add of 64-float messages (16 lanes per edge, float4 each) ----
__global__ void scatter64_kernel(const float4* __restrict__ h,   // [n][16] float4
                                 const int* __restrict__ src,
                                 const int* __restrict__ dst,
                                 float4* __restrict__ acc,       // [n][16] float4
                                 int E) {
    int i = blockIdx.x * blockDim.x + threadIdx.x;  // item = edge*16 + j
    int total = E * 16;
    if (i >= total) return;
    int e = i >> 4;
    int j = i & 15;
    int s = __ldg(&src[e]);
    int d = __ldg(&dst[e]);
    float4 v = __ldg(&h[(size_t)s * 16 + j]);
    float* p = (float*)&acc[(size_t)d * 16 + j];
    asm volatile("red.global.add.v4.f32 [%0], {%1,%2,%3,%4};"
                 :: "l"(p), "f"(v.x), "f"(v.y), "f"(v.z), "f"(v.w) : "memory");
}

// ---------------- generic concat-GEMM:  C = [A1 | A2*invdeg] @ W + bias ----------------
// A1: [n, K1], A2: [n, K2] (optional, scaled per-row by invdeg), W: [(K1+K2), OUT] row-major
template<int K1, int K2, int OUT, bool RELU>
__global__ void gemm_cat_kernel(const float* __restrict__ A1,
                                const float* __restrict__ A2,
                                const float* __restrict__ invdeg,
                                const float* __restrict__ W,
                                const float* __restrict__ bias,
                                float* __restrict__ C, int n)
{
    constexpr int K  = K1 + K2;
    constexpr int BM = 64;
    constexpr int BK = 16;
    constexpr int TM = 4;
    constexpr int TN = OUT / 16;   // 2, 4 or 8

    __shared__ float As[BM][BK + 1];
    __shared__ float Ws[BK][OUT];

    const int tid  = threadIdx.x;    // 256 threads
    const int tx   = tid & 15;       // column lane group
    const int ty   = tid >> 4;       // row lane group
    const int row0 = blockIdx.x * BM;

    float acc[TM][TN];
#pragma unroll
    for (int i = 0; i < TM; i++)
#pragma unroll
        for (int j = 0; j < TN; j++) acc[i][j] = 0.f;

    for (int kt = 0; kt < K; kt += BK) {
        // ---- load A tile (BM x BK), 4 elements per thread ----
#pragma unroll
        for (int p = 0; p < 4; p++) {
            int r    = ty + p * 16;
            int kk   = tx;
            int grow = row0 + r;
            int gk   = kt + kk;
            float v  = 0.f;
            if (grow < n) {
                if (K2 == 0 || gk < K1) {
                    v = A1[(size_t)grow * K1 + gk];
                } else {
                    v = A2[(size_t)grow * K2 + (gk - K1)] * __ldg(&invdeg[grow]);
                }
            }
            As[r][kk] = v;
        }
        // ---- load W tile (BK x OUT) ----
#pragma unroll
        for (int idx = tid; idx < BK * OUT; idx += 256) {
            int k = idx / OUT;
            int c = idx % OUT;
            Ws[k][c] = W[(size_t)(kt + k) * OUT + c];
        }
        __syncthreads();

#pragma unroll
        for (int k = 0; k < BK; k++) {
            float a[TM], b[TN];
#pragma unroll
            for (int i = 0; i < TM; i++) a[i] = As[ty + 16 * i][k];
#pragma unroll
            for (int j = 0; j < TN; j++) b[j] = Ws[k][tx + 16 * j];
#pragma unroll
            for (int i = 0; i < TM; i++)
#pragma unroll
                for (int j = 0; j < TN; j++)
                    acc[i][j] = fmaf(a[i], b[j], acc[i][j]);
        }
        __syncthreads();
    }

#pragma unroll
    for (int i = 0; i < TM; i++) {
        int grow = row0 + ty + 16 * i;
        if (grow >= n) continue;
#pragma unroll
        for (int j = 0; j < TN; j++) {
            int c   = tx + 16 * j;
            float v = acc[i][j] + bias[c];
            if (RELU) v = fmaxf(v, 0.f);
            C[(size_t)grow * OUT + c] = v;
        }
    }
}

// ---------------- head: out = relu(x2 @ Wl1 + bl1) @ Wl2 + bl2  (warp per row) ----------
__global__ void head_kernel(const float* __restrict__ x2,
                            const float* __restrict__ Wl1,  // [64,32]
                            const float* __restrict__ bl1,  // [32]
                            const float* __restrict__ Wl2,  // [32,1]
                            const float* __restrict__ bl2,  // [1]
                            float* __restrict__ out, int n)
{
    int gtid = blockIdx.x * blockDim.x + threadIdx.x;
    int row  = gtid >> 5;
    int lane = gtid & 31;
    if (row >= n) return;

    const float* xr = x2 + (size_t)row * 64;
    float acc = 0.f;
#pragma unroll
    for (int k = 0; k < 64; k++)
        acc = fmaf(__ldg(&xr[k]), __ldg(&Wl1[k * 32 + lane]), acc);
    float h = fmaxf(acc + __ldg(&bl1[lane]), 0.f);
    float p = h * __ldg(&Wl2[lane]);
#pragma unroll
    for (int off = 16; off; off >>= 1)
        p += __shfl_down_sync(0xffffffffu, p, off);
    if (lane == 0) out[row] = p + __ldg(&bl2[0]);
}

// ---------------- launch ----------------
extern "C" void kernel_launch(void* const* d_in, const int* in_sizes, int n_in,
                              void* d_out, int out_size)
{
    const float* x    = (const float*)d_in[0];
    const int*   ei   = (const int*)  d_in[1];
    // d_in[2] = edge_attr (unused by the reference computation)
    const float* W1a  = (const float*)d_in[3];
    const float* b1a  = (const float*)d_in[4];
    const float* W1b  = (const float*)d_in[5];
    const float* b1b  = (const float*)d_in[6];
    const float* W2a  = (const float*)d_in[7];
    const float* b2a  = (const float*)d_in[8];
    const float* W2b  = (const float*)d_in[9];
    const float* b2b  = (const float*)d_in[10];
    const float* Wl1  = (const float*)d_in[11];
    const float* bl1  = (const float*)d_in[12];
    const float* Wl2  = (const float*)d_in[13];
    const float* bl2  = (const float*)d_in[14];
    float* out = (float*)d_out;

    const int N = in_sizes[0] / INDIM;
    const int E = in_sizes[1] / 2;
    const int* src = ei;
    const int* dst = ei + E;

    // resolve scratch addresses
    float *h, *m, *x1, *x2, *deg;
    cudaGetSymbolAddress((void**)&h,   g_h);
    cudaGetSymbolAddress((void**)&m,   g_m);
    cudaGetSymbolAddress((void**)&x1,  g_x1);
    cudaGetSymbolAddress((void**)&x2,  g_x2);
    cudaGetSymbolAddress((void**)&deg, g_deg);

    const int T = 256;
    auto blocks = [](long long work, int t) { return (int)((work + t - 1) / t); };

    // degree (shared by both layers)
    zero_kernel<<<blocks(N, T), T>>>(deg, N);
    degree_kernel<<<blocks(E, T), T>>>(dst, deg, E);
    invdeg_kernel<<<blocks(N, T), T>>>(deg, N);

    // ---- layer 1 ----
    zero_kernel<<<blocks((long long)N * 64, T), T>>>(m, N * 64);
    gemm_cat_kernel<256, 0, 64, false><<<blocks(N, 64), 256>>>(x, nullptr, nullptr, W1a, b1a, h, N);
    scatter64_kernel<<<blocks((long long)E * 16, T), T>>>((const float4*)h, src, dst, (float4*)m, E);
    gemm_cat_kernel<256, 64, 128, true><<<blocks(N, 64), 256>>>(x, m, deg, W1b, b1b, x1, N);

    // ---- layer 2 ----
    zero_kernel<<<blocks((long long)N * 64, T), T>>>(m, N * 64);
    gemm_cat_kernel<128, 0, 64, false><<<blocks(N, 64), 256>>>(x1, nullptr, nullptr, W2a, b2a, h, N);
    scatter64_kernel<<<blocks((long long)E * 16, T), T>>>((const float4*)h, src, dst, (float4*)m, E);
    gemm_cat_kernel<128, 64, 64, true><<<blocks(N, 64), 256>>>(x1, m, deg, W2b, b2b, x2, N);

    // ---- head ----
    head_kernel<<<blocks((long long)N * 32, T), T>>>(x2, Wl1, bl1, Wl2, bl2, out, N);
}

// round 2
// speedup vs baseline: 1.3493x; 1.3493x over previous
#include <cuda_runtime.h>
#include <cstdint>

#define NMAX 100000
#define INDIM 256

// ---------------- device scratch ----------------
__device__ float g_h [NMAX * 64];
__device__ float g_m [NMAX * 64];
__device__ float g_x1[NMAX * 128];
__device__ float g_x2[NMAX * 64];
__device__ float g_deg[NMAX];

// ---------------- f32x2 packed math helpers ----------------
__device__ __forceinline__ unsigned long long pack2(float lo, float hi) {
    unsigned long long r;
    asm("mov.b64 %0, {%1,%2};" : "=l"(r) : "f"(lo), "f"(hi));
    return r;
}
__device__ __forceinline__ unsigned long long fma2(unsigned long long a,
                                                   unsigned long long b,
                                                   unsigned long long c) {
    unsigned long long d;
    asm("fma.rn.f32x2 %0, %1, %2, %3;" : "=l"(d) : "l"(a), "l"(b), "l"(c));
    return d;
}
__device__ __forceinline__ float2 unpack2(unsigned long long v) {
    float2 f;
    asm("mov.b64 {%0,%1}, %2;" : "=f"(f.x), "=f"(f.y) : "l"(v));
    return f;
}

// ---------------- small utility kernels ----------------
__global__ void zero4_kernel(float4* __restrict__ p, int n4) {
    int i = blockIdx.x * blockDim.x + threadIdx.x;
    if (i < n4) p[i] = make_float4(0.f, 0.f, 0.f, 0.f);
}

__global__ void degree_kernel(const int* __restrict__ dst, float* __restrict__ deg, int E) {
    int e = blockIdx.x * blockDim.x + threadIdx.x;
    if (e < E) atomicAdd(&deg[dst[e]], 1.0f);
}

__global__ void invdeg_kernel(float* __restrict__ deg, int n) {
    int i = blockIdx.x * blockDim.x + threadIdx.x;
    if (i < n) deg[i] = 1.0f / fmaxf(deg[i], 1.0f);
}

// ---------------- scatter-add of 64-float messages ----------------
__global__ void scatter64_kernel(const float4* __restrict__ h,
                                 const int* __restrict__ src,
                                 const int* __restrict__ dst,
                                 float4* __restrict__ acc,
                                 int E) {
    int i = blockIdx.x * blockDim.x + threadIdx.x;
    int total = E * 16;
    if (i >= total) return;
    int e = i >> 4;
    int j = i & 15;
    int s = __ldg(&src[e]);
    int d = __ldg(&dst[e]);
    float4 v = __ldg(&h[(size_t)s * 16 + j]);
    float* p = (float*)&acc[(size_t)d * 16 + j];
    asm volatile("red.global.add.v4.f32 [%0], {%1,%2,%3,%4};"
                 :: "l"(p), "f"(v.x), "f"(v.y), "f"(v.z), "f"(v.w) : "memory");
}

// ---------------- concat-GEMM with packed f32x2 FMA ----------------
// C = relu?( [A1 | A2*invdeg] @ W + bias )
// A1:[n,K1]  A2:[n,K2]  W:[(K1+K2),OUT] row-major
template<int K1, int K2, int OUT, bool RELU>
__global__ __launch_bounds__(256, 2)
void gemm_cat2(const float* __restrict__ A1,
               const float* __restrict__ A2,
               const float* __restrict__ invdeg,
               const float* __restrict__ W,
               const float* __restrict__ bias,
               float* __restrict__ C, int n)
{
    constexpr int K   = K1 + K2;
    constexpr int BM  = 128;
    constexpr int BK  = 32;
    constexpr int TN  = OUT / 16;   // 4 (OUT=64) or 8 (OUT=128)
    constexpr int NP  = TN / 2;     // f32x2 pairs per row
    constexpr int LDA = BM + 4;     // keeps 16B alignment of rows

    static_assert(K % BK == 0, "K must be multiple of BK");
    static_assert(K1 % 4 == 0, "K1 must be multiple of 4");

    __shared__ float As[BK][LDA];   // k-major (transposed) A tile
    __shared__ float Ws[BK][OUT];

    const int tid  = threadIdx.x;
    const int tx   = tid & 15;
    const int ty   = tid >> 4;
    const int row0 = blockIdx.x * BM;

    unsigned long long acc[8][NP];
#pragma unroll
    for (int i = 0; i < 8; i++)
#pragma unroll
        for (int j = 0; j < NP; j++) acc[i][j] = 0ull;  // {0.f,0.f}

    for (int kt = 0; kt < K; kt += BK) {
        // ---- A tile: 128 rows x 32 k = 1024 float4, 4 per thread, transposed store ----
#pragma unroll
        for (int p = 0; p < 4; p++) {
            int idx  = tid + p * 256;
            int r    = idx >> 3;        // 0..127
            int kc   = idx & 7;         // float4 chunk along k
            int grow = row0 + r;
            int gk   = kt + kc * 4;
            float4 v = make_float4(0.f, 0.f, 0.f, 0.f);
            if (grow < n) {
                if (K2 == 0 || gk < K1) {
                    v = *(const float4*)&A1[(size_t)grow * K1 + gk];
                } else {
                    v = *(const float4*)&A2[(size_t)grow * K2 + (gk - K1)];
                    float s = __ldg(&invdeg[grow]);
                    v.x *= s; v.y *= s; v.z *= s; v.w *= s;
                }
            }
            As[kc * 4 + 0][r] = v.x;
            As[kc * 4 + 1][r] = v.y;
            As[kc * 4 + 2][r] = v.z;
            As[kc * 4 + 3][r] = v.w;
        }
        // ---- W tile: BK x OUT ----
#pragma unroll
        for (int p = 0; p < (BK * OUT) / 1024; p++) {
            int idx = tid + p * 256;
            int kr  = idx / (OUT / 4);
            int c4  = idx % (OUT / 4);
            *(float4*)&Ws[kr][c4 * 4] =
                *(const float4*)&W[(size_t)(kt + kr) * OUT + c4 * 4];
        }
        __syncthreads();

#pragma unroll
        for (int k = 0; k < BK; k++) {
            float4 a0 = *(const float4*)&As[k][ty * 8];
            float4 a1 = *(const float4*)&As[k][ty * 8 + 4];
            float ar[8] = {a0.x, a0.y, a0.z, a0.w, a1.x, a1.y, a1.z, a1.w};

            unsigned long long bp[NP];
            {
                float4 b0 = *(const float4*)&Ws[k][tx * TN];
                bp[0] = pack2(b0.x, b0.y);
                bp[1] = pack2(b0.z, b0.w);
                if constexpr (NP == 4) {
                    float4 b1 = *(const float4*)&Ws[k][tx * TN + 4];
                    bp[2] = pack2(b1.x, b1.y);
                    bp[3] = pack2(b1.z, b1.w);
                }
            }
#pragma unroll
            for (int i = 0; i < 8; i++) {
                unsigned long long aa = pack2(ar[i], ar[i]);
#pragma unroll
                for (int j = 0; j < NP; j++)
                    acc[i][j] = fma2(aa, bp[j], acc[i][j]);
            }
        }
        __syncthreads();
    }

    // ---- epilogue ----
#pragma unroll
    for (int i = 0; i < 8; i++) {
        int grow = row0 + ty * 8 + i;
        if (grow >= n) continue;
#pragma unroll
        for (int j = 0; j < NP; j++) {
            float2 v = unpack2(acc[i][j]);
            int c = tx * TN + j * 2;
            v.x += bias[c];
            v.y += bias[c + 1];
            if (RELU) { v.x = fmaxf(v.x, 0.f); v.y = fmaxf(v.y, 0.f); }
            *(float2*)&C[(size_t)grow * OUT + c] = v;
        }
    }
}

// ---------------- head: out = relu(x2 @ Wl1 + bl1) @ Wl2 + bl2 ----------------
__global__ void head_kernel(const float* __restrict__ x2,
                            const float* __restrict__ Wl1,
                            const float* __restrict__ bl1,
                            const float* __restrict__ Wl2,
                            const float* __restrict__ bl2,
                            float* __restrict__ out, int n)
{
    int gtid = blockIdx.x * blockDim.x + threadIdx.x;
    int row  = gtid >> 5;
    int lane = gtid & 31;
    if (row >= n) return;

    const float* xr = x2 + (size_t)row * 64;
    float acc = 0.f;
#pragma unroll
    for (int k = 0; k < 64; k++)
        acc = fmaf(__ldg(&xr[k]), __ldg(&Wl1[k * 32 + lane]), acc);
    float h = fmaxf(acc + __ldg(&bl1[lane]), 0.f);
    float p = h * __ldg(&Wl2[lane]);
#pragma unroll
    for (int off = 16; off; off >>= 1)
        p += __shfl_down_sync(0xffffffffu, p, off);
    if (lane == 0) out[row] = p + __ldg(&bl2[0]);
}

// ---------------- launch ----------------
extern "C" void kernel_launch(void* const* d_in, const int* in_sizes, int n_in,
                              void* d_out, int out_size)
{
    const float* x    = (const float*)d_in[0];
    const int*   ei   = (const int*)  d_in[1];
    const float* W1a  = (const float*)d_in[3];
    const float* b1a  = (const float*)d_in[4];
    const float* W1b  = (const float*)d_in[5];
    const float* b1b  = (const float*)d_in[6];
    const float* W2a  = (const float*)d_in[7];
    const float* b2a  = (const float*)d_in[8];
    const float* W2b  = (const float*)d_in[9];
    const float* b2b  = (const float*)d_in[10];
    const float* Wl1  = (const float*)d_in[11];
    const float* bl1  = (const float*)d_in[12];
    const float* Wl2  = (const float*)d_in[13];
    const float* bl2  = (const float*)d_in[14];
    float* out = (float*)d_out;

    const int N = in_sizes[0] / INDIM;
    const int E = in_sizes[1] / 2;
    const int* src = ei;
    const int* dst = ei + E;

    float *h, *m, *x1, *x2, *deg;
    cudaGetSymbolAddress((void**)&h,   g_h);
    cudaGetSymbolAddress((void**)&m,   g_m);
    cudaGetSymbolAddress((void**)&x1,  g_x1);
    cudaGetSymbolAddress((void**)&x2,  g_x2);
    cudaGetSymbolAddress((void**)&deg, g_deg);

    const int T = 256;
    auto blocks = [](long long work, int t) { return (int)((work + t - 1) / t); };
    const int gemm_grid = blocks(N, 128);

    // degree (shared by both layers)
    zero4_kernel<<<blocks((N + 3) / 4, T), T>>>((float4*)deg, (N + 3) / 4);
    degree_kernel<<<blocks(E, T), T>>>(dst, deg, E);
    invdeg_kernel<<<blocks(N, T), T>>>(deg, N);

    // ---- layer 1 ----
    zero4_kernel<<<blocks((long long)N * 16, T), T>>>((float4*)m, N * 16);
    gemm_cat2<256, 0, 64, false><<<gemm_grid, 256>>>(x, nullptr, nullptr, W1a, b1a, h, N);
    scatter64_kernel<<<blocks((long long)E * 16, T), T>>>((const float4*)h, src, dst, (float4*)m, E);
    gemm_cat2<256, 64, 128, true><<<gemm_grid, 256>>>(x, m, deg, W1b, b1b, x1, N);

    // ---- layer 2 ----
    zero4_kernel<<<blocks((long long)N * 16, T), T>>>((float4*)m, N * 16);
    gemm_cat2<128, 0, 64, false><<<gemm_grid, 256>>>(x1, nullptr, nullptr, W2a, b2a, h, N);
    scatter64_kernel<<<blocks((long long)E * 16, T), T>>>((const float4*)h, src, dst, (float4*)m, E);
    gemm_cat2<128, 64, 64, true><<<gemm_grid, 256>>>(x1, m, deg, W2b, b2b, x2, N);

    // ---- head ----
    head_kernel<<<blocks((long long)N * 32, T), T>>>(x2, Wl1, bl1, Wl2, bl2, out, N);
}